// round 14
// baseline (speedup 1.0000x reference)
#include <cuda_runtime.h>
#include <cuda_bf16.h>
#include <math.h>
#include <stdint.h>

#define B_SESS   8192
#define NPS      21
#define N_NODES  (B_SESS * NPS)      // 172032
#define F_IN     171
#define K1_PAD   192                 // F_IN padded to 6*32
#define F_HID    256
#define F_OUT    128

// GEMM2 blocking
#define SESS_PER_BLK 6
#define ROWS_PER_BLK (SESS_PER_BLK * NPS)   // 126
#define NBLK ((B_SESS + SESS_PER_BLK - 1) / SESS_PER_BLK)  // 1366

// GEMM1 blocking (3 sessions, 64-row tile, 2 CTAs/SM)
#define G1_SESS 3
#define G1_ROWS (G1_SESS * NPS)             // 63
#define G1_NBLK ((B_SESS + G1_SESS - 1) / G1_SESS)  // 2731

// Output layout: hidden_state (N*128) | y (N*1) | x (N*171)
#define OUT_HID_OFF  0
#define OUT_Y_OFF    ((size_t)N_NODES * F_OUT)
#define OUT_X_OFF    ((size_t)N_NODES * (F_OUT + 1))

// Scratch (static device arrays: allocation-free)
__device__ __nv_bfloat16  g_xhi[(size_t)N_NODES * K1_PAD];
__device__ __nv_bfloat16  g_xlo[(size_t)N_NODES * K1_PAD];
__device__ __nv_bfloat16  g_yhi[(size_t)N_NODES * F_HID];
__device__ __nv_bfloat16  g_ylo[(size_t)N_NODES * F_HID];
__device__ __nv_bfloat16  g_w1hi[(size_t)F_HID * K1_PAD];
__device__ __nv_bfloat16  g_w1lo[(size_t)F_HID * K1_PAD];
__device__ __nv_bfloat16  g_w2hi[(size_t)F_OUT * F_HID];
__device__ __nv_bfloat16  g_w2lo[(size_t)F_OUT * F_HID];

// ===========================================================================
// helpers
// ===========================================================================
__device__ __forceinline__ uint32_t smem_to_u32(const void* p) {
    uint32_t a;
    asm("{ .reg .u64 t; cvta.to.shared.u64 t, %1; cvt.u32.u64 %0, t; }" : "=r"(a) : "l"(p));
    return a;
}
__device__ __forceinline__ void cp_async16(uint32_t dst, const void* src) {
    asm volatile("cp.async.cg.shared.global [%0], [%1], 16;" :: "r"(dst), "l"(src));
}
#define CP_COMMIT() asm volatile("cp.async.commit_group;" ::: "memory")
#define CP_WAIT0()  asm volatile("cp.async.wait_group 0;" ::: "memory")
#define CP_WAIT1()  asm volatile("cp.async.wait_group 1;" ::: "memory")

__device__ __forceinline__ void ldsm_x4(uint32_t addr, uint32_t* r) {
    asm volatile("ldmatrix.sync.aligned.m8n8.x4.shared.b16 {%0,%1,%2,%3}, [%4];"
        : "=r"(r[0]), "=r"(r[1]), "=r"(r[2]), "=r"(r[3]) : "r"(addr));
}
__device__ __forceinline__ void mma_bf16(float* d, const uint32_t* a, const uint32_t* b) {
    asm volatile("mma.sync.aligned.m16n8k16.row.col.f32.bf16.bf16.f32 "
        "{%0,%1,%2,%3}, {%4,%5,%6,%7}, {%8,%9}, {%0,%1,%2,%3};"
        : "+f"(d[0]), "+f"(d[1]), "+f"(d[2]), "+f"(d[3])
        : "r"(a[0]), "r"(a[1]), "r"(a[2]), "r"(a[3]), "r"(b[0]), "r"(b[1]));
}

// XOR bank swizzle on 64B rows (16B chunk granularity)
__device__ __forceinline__ uint32_t sw_off(int row, int colByte) {
    return (uint32_t)(row * 64 + ((((colByte >> 4) ^ ((row >> 1) & 3)) & 3) << 4));
}

__device__ __forceinline__ float lrelu(float v) { return v > 0.f ? v : 0.2f * v; }

// Branch-specialized softmax over in-neighbors (no local arrays).
__device__ __forceinline__ void compute_alpha(
    const float* __restrict__ sv, const float* __restrict__ dvv,
    float* __restrict__ alpha, int node)
{
    int slot = node % NPS;
    int rbase = node - slot;
    float d = dvv[node];
    float* al = alpha + node * 12;
    if (slot == 0) {
        float e0 = lrelu(sv[rbase + 1] + d);
        float e1 = lrelu(sv[rbase + 2] + d);
        float e2 = lrelu(sv[rbase + 3] + d);
        float e3 = lrelu(sv[rbase + 4] + d);
        float e4 = lrelu(sv[rbase + 5] + d);
        float e5 = lrelu(sv[rbase + 6] + d);
        float e6 = lrelu(sv[rbase + 7] + d);
        float e7 = lrelu(sv[rbase + 8] + d);
        float e8 = lrelu(sv[rbase + 9] + d);
        float e9 = lrelu(sv[rbase + 10] + d);
        float ea = lrelu(sv[rbase + 0] + d);
        float m = fmaxf(ea, fmaxf(fmaxf(fmaxf(e0, e1), fmaxf(e2, e3)),
                  fmaxf(fmaxf(fmaxf(e4, e5), fmaxf(e6, e7)), fmaxf(e8, e9))));
        e0 = expf(e0 - m); e1 = expf(e1 - m); e2 = expf(e2 - m); e3 = expf(e3 - m);
        e4 = expf(e4 - m); e5 = expf(e5 - m); e6 = expf(e6 - m); e7 = expf(e7 - m);
        e8 = expf(e8 - m); e9 = expf(e9 - m); ea = expf(ea - m);
        float inv = 1.f / (e0 + e1 + e2 + e3 + e4 + e5 + e6 + e7 + e8 + e9 + ea);
        al[0] = e0 * inv; al[1] = e1 * inv; al[2] = e2 * inv; al[3] = e3 * inv;
        al[4] = e4 * inv; al[5] = e5 * inv; al[6] = e6 * inv; al[7] = e7 * inv;
        al[8] = e8 * inv; al[9] = e9 * inv; al[10] = ea * inv;
    } else if (slot <= 10) {
        float v0 = lrelu(sv[rbase] + d);
        float v1 = lrelu(sv[rbase + slot + 10] + d);
        float v2 = lrelu(sv[rbase + slot] + d);
        float m = fmaxf(v0, fmaxf(v1, v2));
        float e0 = expf(v0 - m), e1 = expf(v1 - m), e2 = expf(v2 - m);
        float inv = 1.f / (e0 + e1 + e2);
        al[0] = e0 * inv; al[1] = e1 * inv; al[2] = e2 * inv;
    } else {
        float v0 = lrelu(sv[rbase + slot - 10] + d);
        float v1 = lrelu(sv[rbase + slot] + d);
        float m = fmaxf(v0, v1);
        float e0 = expf(v0 - m), e1 = expf(v1 - m);
        float inv = 1.f / (e0 + e1);
        al[0] = e0 * inv; al[1] = e1 * inv;
    }
}

// Branch-specialized 4-column aggregation (float4, explicit slot).
__device__ __forceinline__ float4 aggregate4(
    const float* __restrict__ hs, int stride,
    const float* __restrict__ alpha, int rbase, int slot, int col0)
{
    const float* al = alpha + (rbase + slot) * 12;
    float4 a = make_float4(0.f, 0.f, 0.f, 0.f);
    if (slot == 0) {
        #pragma unroll
        for (int j = 0; j < 10; j++) {
            float4 h = *(const float4*)&hs[(rbase + 1 + j) * stride + col0];
            float w = al[j];
            a.x = fmaf(w, h.x, a.x); a.y = fmaf(w, h.y, a.y);
            a.z = fmaf(w, h.z, a.z); a.w = fmaf(w, h.w, a.w);
        }
        float4 h = *(const float4*)&hs[rbase * stride + col0];
        float w = al[10];
        a.x = fmaf(w, h.x, a.x); a.y = fmaf(w, h.y, a.y);
        a.z = fmaf(w, h.z, a.z); a.w = fmaf(w, h.w, a.w);
    } else if (slot <= 10) {
        float4 h0 = *(const float4*)&hs[rbase * stride + col0];
        float4 h1 = *(const float4*)&hs[(rbase + slot + 10) * stride + col0];
        float4 h2 = *(const float4*)&hs[(rbase + slot) * stride + col0];
        float w0 = al[0], w1 = al[1], w2 = al[2];
        a.x = w0 * h0.x + w1 * h1.x + w2 * h2.x;
        a.y = w0 * h0.y + w1 * h1.y + w2 * h2.y;
        a.z = w0 * h0.z + w1 * h1.z + w2 * h2.z;
        a.w = w0 * h0.w + w1 * h1.w + w2 * h2.w;
    } else {
        float4 h0 = *(const float4*)&hs[(rbase + slot - 10) * stride + col0];
        float4 h1 = *(const float4*)&hs[(rbase + slot) * stride + col0];
        float w0 = al[0], w1 = al[1];
        a.x = w0 * h0.x + w1 * h1.x;
        a.y = w0 * h0.y + w1 * h1.y;
        a.z = w0 * h0.z + w1 * h1.z;
        a.w = w0 * h0.w + w1 * h1.w;
    }
    return a;
}

__device__ __forceinline__ uint2 pack_hi_lo4(float v0, float v1, float v2, float v3,
                                             uint2& lo_out)
{
    __nv_bfloat16 h0 = __float2bfloat16(v0), h1 = __float2bfloat16(v1);
    __nv_bfloat16 h2 = __float2bfloat16(v2), h3 = __float2bfloat16(v3);
    __nv_bfloat16 l0 = __float2bfloat16(v0 - __bfloat162float(h0));
    __nv_bfloat16 l1 = __float2bfloat16(v1 - __bfloat162float(h1));
    __nv_bfloat16 l2 = __float2bfloat16(v2 - __bfloat162float(h2));
    __nv_bfloat16 l3 = __float2bfloat16(v3 - __bfloat162float(h3));
    __nv_bfloat162 h01(h0, h1), h23(h2, h3), l01(l0, l1), l23(l2, l3);
    uint2 hi;
    hi.x = *reinterpret_cast<uint32_t*>(&h01);
    hi.y = *reinterpret_cast<uint32_t*>(&h23);
    lo_out.x = *reinterpret_cast<uint32_t*>(&l01);
    lo_out.y = *reinterpret_cast<uint32_t*>(&l23);
    return hi;
}

// ===========================================================================
// Kernel 1: build x_mod (scatter) + fused bf16 hi/lo split, 4 cols per thread
// ===========================================================================
__global__ __launch_bounds__(256) void build_x_kernel(
    const float* __restrict__ x,
    const int*   __restrict__ click,
    const int*   __restrict__ query,
    const int*   __restrict__ docu,
    const int*   __restrict__ title_id,
    const float* __restrict__ qtab,
    const float* __restrict__ dtab,
    const float* __restrict__ ttab,
    const float* __restrict__ ptab,
    const float* __restrict__ ctab,
    float* __restrict__ xout,
    __nv_bfloat16* __restrict__ xhi,
    __nv_bfloat16* __restrict__ xlo)
{
    long long t = (long long)blockIdx.x * blockDim.x + threadIdx.x;
    if (t >= (long long)N_NODES * (K1_PAD / 4)) return;
    int n  = (int)(t / (K1_PAD / 4));
    int cc = (int)(t - (long long)n * (K1_PAD / 4));
    int c0 = cc * 4;
    int b = n / NPS;
    int s = n - b * NPS;

    float4 v;
    if (c0 + 3 < 160) {
        const float* tab;
        size_t row;
        if (s == 0)            { tab = qtab; row = (size_t)query[b]; }
        else if (s <= 10)      { tab = dtab; row = (size_t)docu[b * 10 + (s - 1)]; }
        else                   { tab = ttab; row = (size_t)title_id[b * 10 + (s - 11)]; }
        v = *(const float4*)(tab + row * 160 + c0);
    } else {
        float vv[4];
        #pragma unroll
        for (int j = 0; j < 4; j++) {
            int c = c0 + j;
            float val = 0.f;
            if (c < F_IN) {
                long long xi = (long long)n * F_IN + c;
                if (s == 0) {
                    val = (c < 160) ? qtab[(size_t)query[b] * 160 + c] : x[xi];
                } else if (s <= 10) {
                    int jj = s - 1;
                    if      (c < 160)  val = dtab[(size_t)docu[b * 10 + jj] * 160 + c];
                    else if (c == 160) val = ptab[jj];
                    else if (c == 161) val = ctab[click[b]];
                    else               val = x[xi];
                } else {
                    val = (c < 160) ? ttab[(size_t)title_id[b * 10 + (s - 11)] * 160 + c] : x[xi];
                }
            }
            vv[j] = val;
        }
        v = make_float4(vv[0], vv[1], vv[2], vv[3]);
    }

    {
        long long xi = (long long)n * F_IN + c0;
        if (c0 + 3 < F_IN) {
            xout[xi] = v.x; xout[xi + 1] = v.y; xout[xi + 2] = v.z; xout[xi + 3] = v.w;
        } else {
            float vv[4] = {v.x, v.y, v.z, v.w};
            #pragma unroll
            for (int j = 0; j < 4; j++)
                if (c0 + j < F_IN) xout[xi + j] = vv[j];
        }
    }

    long long oi = (long long)n * K1_PAD + c0;
    uint2 lo;
    uint2 hi = pack_hi_lo4(v.x, v.y, v.z, v.w, lo);
    *(uint2*)(xhi + oi) = hi;
    *(uint2*)(xlo + oi) = lo;
}

// ===========================================================================
// Kernel 2: fp32 -> bf16 hi/lo split for weights (with K padding)
// ===========================================================================
__global__ __launch_bounds__(256) void conv_split(
    const float* __restrict__ src, int Ksrc,
    __nv_bfloat16* __restrict__ hi, __nv_bfloat16* __restrict__ lo,
    int Kdst, long long total)
{
    long long idx = (long long)blockIdx.x * blockDim.x + threadIdx.x;
    if (idx >= total) return;
    long long row = idx / Kdst;
    int c = (int)(idx - row * Kdst);
    float v = (c < Ksrc) ? src[row * Ksrc + c] : 0.f;
    __nv_bfloat16 h = __float2bfloat16(v);
    hi[idx] = h;
    lo[idx] = __float2bfloat16(v - __bfloat162float(h));
}

// ===========================================================================
// Kernel 3: fused GEMM1 (x @ W1^T, split-3 bf16 HMMA) + GAT agg layer 1
// Block: 256 thr, 8 warps (2x4), tile 64(63 used) x 256, K=192. 2-stage.
// Mainloop: batch-issue all 12 ldmatrix per ks, then 48 MMAs uninterrupted.
// ===========================================================================
#define G1_NK 6
#define G1_ARRA 4096            // 64 rows x 64B
#define G1_ARRB 16384           // 256 rows x 64B
#define G1_STAGE_B (2 * G1_ARRA + 2 * G1_ARRB)   // 40960
#define G1_SMEM (2 * G1_STAGE_B)   // 81920
#define HS1_STRIDE 260

__global__ __launch_bounds__(256, 2) void gemm1_fused(
    const __nv_bfloat16* __restrict__ Ahi, const __nv_bfloat16* __restrict__ Alo,
    const __nv_bfloat16* __restrict__ Bhi, const __nv_bfloat16* __restrict__ Blo,
    const float* __restrict__ asrc, const float* __restrict__ adst,
    const float* __restrict__ bias,
    __nv_bfloat16* __restrict__ Yhi, __nv_bfloat16* __restrict__ Ylo)
{
    extern __shared__ char smem[];
    const uint32_t sb = smem_to_u32(smem);
    const int tid = threadIdx.x;
    const int wid = tid >> 5, lane = tid & 31;
    const int warpM = wid & 1, warpN = wid >> 1;     // 2 x 4 warp grid
    const int rowBaseI = blockIdx.x * G1_ROWS;

    const __nv_bfloat16* srcA[2] = { Ahi + (size_t)rowBaseI * K1_PAD,
                                     Alo + (size_t)rowBaseI * K1_PAD };
    const __nv_bfloat16* srcB[2] = { Bhi, Blo };

    auto load_stage = [&](int ck, int st) {
        uint32_t base = sb + st * G1_STAGE_B;
        #pragma unroll
        for (int i = 0; i < 10; i++) {
            int id = tid + i * 256;            // 0..2559
            if (id < 512) {                    // A arrays: 2 x 64 rows
                int m = id >> 8;
                int v = id & 255;
                int row = v >> 2, c = v & 3;
                int rowc = row;
                if (rowBaseI + rowc >= N_NODES) rowc = N_NODES - 1 - rowBaseI;
                const char* g = (const char*)(srcA[m] + (size_t)rowc * K1_PAD + ck * 32) + c * 16;
                cp_async16(base + m * G1_ARRA + sw_off(row, c * 16), g);
            } else {                           // B arrays: 2 x 256 rows
                int idb = id - 512;
                int m = idb >> 10;
                int v = idb & 1023;
                int row = v >> 2, c = v & 3;
                const char* g = (const char*)(srcB[m] + (size_t)row * K1_PAD + ck * 32) + c * 16;
                cp_async16(base + 2 * G1_ARRA + m * G1_ARRB + sw_off(row, c * 16), g);
            }
        }
        CP_COMMIT();
    };

    float acc[2][8][4];
    #pragma unroll
    for (int mt = 0; mt < 2; mt++)
        #pragma unroll
        for (int nt = 0; nt < 8; nt++)
            #pragma unroll
            for (int j = 0; j < 4; j++) acc[mt][nt][j] = 0.f;

    load_stage(0, 0);

    const int q = lane >> 3, r = lane & 7;
    const int aRowBase = warpM * 32 + ((q & 1) ? 8 : 0) + r;
    const int aColSel  = (q & 2) ? 8 : 0;
    const int bRowBase = warpN * 64 + ((q & 2) ? 8 : 0) + r;
    const int bColSel  = (q & 1) ? 8 : 0;

    #pragma unroll
    for (int ck = 0; ck < G1_NK; ck++) {
        CP_WAIT0();
        __syncthreads();
        if (ck + 1 < G1_NK) load_stage(ck + 1, (ck + 1) & 1);

        const uint32_t st = sb + (ck & 1) * G1_STAGE_B;
        #pragma unroll
        for (int ks = 0; ks < 2; ks++) {
            const int k0 = ks * 16;
            // batch-issue ALL fragment loads for this ks
            uint32_t ah[2][4], al[2][4];
            uint32_t bhf[4][4], blf[4][4];
            #pragma unroll
            for (int mt = 0; mt < 2; mt++) {
                uint32_t a = st + sw_off(aRowBase + mt * 16, (k0 + aColSel) * 2);
                ldsm_x4(a, ah[mt]);
                ldsm_x4(a + G1_ARRA, al[mt]);
            }
            #pragma unroll
            for (int nt2 = 0; nt2 < 4; nt2++) {
                uint32_t a = st + 2 * G1_ARRA + sw_off(bRowBase + nt2 * 16, (k0 + bColSel) * 2);
                ldsm_x4(a, bhf[nt2]);
                ldsm_x4(a + G1_ARRB, blf[nt2]);
            }
            // uninterrupted MMA stream
            #pragma unroll
            for (int nt2 = 0; nt2 < 4; nt2++) {
                #pragma unroll
                for (int half = 0; half < 2; half++) {
                    const int nt = nt2 * 2 + half;
                    const uint32_t* bhp = bhf[nt2] + half * 2;
                    const uint32_t* blp = blf[nt2] + half * 2;
                    mma_bf16(acc[0][nt], ah[0], bhp);
                    mma_bf16(acc[1][nt], ah[1], bhp);
                    mma_bf16(acc[0][nt], al[0], bhp);
                    mma_bf16(acc[1][nt], al[1], bhp);
                    mma_bf16(acc[0][nt], ah[0], blp);
                    mma_bf16(acc[1][nt], ah[1], blp);
                }
            }
        }
    }

    // ---------------- fused epilogue: GAT aggregation ----------------
    __syncthreads();   // all warps done reading stages: reuse smem

    float* hs    = (float*)smem;                       // [64][260] = 66560B
    float* sv    = (float*)(smem + 66560);             // 64
    float* dvv   = sv + 64;                            // 64
    float* alpha = dvv + 64;                           // [64][12]
    float* sa    = alpha + 64 * 12;                    // 256
    float* sd    = sa + 256;                           // 256

    const int g2 = lane >> 2, ti = lane & 3;
    #pragma unroll
    for (int mt = 0; mt < 2; mt++) {
        int row = warpM * 32 + mt * 16 + g2;
        #pragma unroll
        for (int nt = 0; nt < 8; nt++) {
            int col = warpN * 64 + nt * 8 + ti * 2;
            *(float2*)&hs[row * HS1_STRIDE + col]       = make_float2(acc[mt][nt][0], acc[mt][nt][1]);
            *(float2*)&hs[(row + 8) * HS1_STRIDE + col] = make_float2(acc[mt][nt][2], acc[mt][nt][3]);
        }
    }
    if (tid < F_HID) { sa[tid] = asrc[tid]; sd[tid] = adst[tid]; }
    __syncthreads();

    const int nSess  = min(G1_SESS, B_SESS - blockIdx.x * G1_SESS);
    const int nNodes = nSess * NPS;

    // per-node attention dots (float4, smem-staged a-vectors)
    {
        const float4* sa4 = (const float4*)sa;
        const float4* sd4 = (const float4*)sd;
        float4 s1 = sa4[lane], s2 = sa4[32 + lane];
        float4 d1 = sd4[lane], d2 = sd4[32 + lane];
        for (int node = wid; node < nNodes; node += 8) {
            const float4* hp = (const float4*)&hs[node * HS1_STRIDE];
            float4 h1 = hp[lane], h2 = hp[32 + lane];
            float ss = h1.x * s1.x + h1.y * s1.y + h1.z * s1.z + h1.w * s1.w
                     + h2.x * s2.x + h2.y * s2.y + h2.z * s2.z + h2.w * s2.w;
            float dd = h1.x * d1.x + h1.y * d1.y + h1.z * d1.z + h1.w * d1.w
                     + h2.x * d2.x + h2.y * d2.y + h2.z * d2.z + h2.w * d2.w;
            #pragma unroll
            for (int o = 16; o; o >>= 1) {
                ss += __shfl_down_sync(0xffffffffu, ss, o);
                dd += __shfl_down_sync(0xffffffffu, dd, o);
            }
            if (lane == 0) { sv[node] = ss; dvv[node] = dd; }
        }
    }
    __syncthreads();

    if (tid < nNodes) compute_alpha(sv, dvv, alpha, tid);
    __syncthreads();

    // aggregate + bias + relu -> y bf16 hi/lo (4 cols per thread)
    {
        const int col0 = (tid & 63) * 4;
        const int hgrp = tid >> 6;              // 0..3 (warp-uniform)
        const float4 bv = *(const float4*)&bias[col0];
        int slot = hgrp;
        for (int n = hgrp; n < nNodes; n += 4) {
            int rbase = n - slot;
            float4 a = aggregate4(hs, HS1_STRIDE, alpha, rbase, slot, col0);
            float v0 = fmaxf(a.x + bv.x, 0.f);
            float v1 = fmaxf(a.y + bv.y, 0.f);
            float v2 = fmaxf(a.z + bv.z, 0.f);
            float v3 = fmaxf(a.w + bv.w, 0.f);
            uint2 lo;
            uint2 hi = pack_hi_lo4(v0, v1, v2, v3, lo);
            size_t off = (size_t)(rowBaseI + n) * F_HID + col0;
            *(uint2*)(Yhi + off) = hi;
            *(uint2*)(Ylo + off) = lo;
            slot += 4; if (slot >= NPS) slot -= NPS;
        }
    }
}

// ===========================================================================
// Kernel 4: fused GEMM2 (y @ W2^T) + GAT agg layer 2 + sigmoid head
// Block: 256 thr, 8 warps (4x2), tile 128(126) x 128, K=256. Batched ldsm.
// ===========================================================================
#define G2_NK 8
#define G2_STAGE_B 32768        // Ahi Alo Bhi Blo: 4 x 8192
#define G2_NSTAGE 3
#define G2_SMEM (G2_NSTAGE * G2_STAGE_B)   // 98304
#define HS2_STRIDE 132

__global__ __launch_bounds__(256, 2) void gemm2_fused(
    const __nv_bfloat16* __restrict__ Ahi, const __nv_bfloat16* __restrict__ Alo,
    const __nv_bfloat16* __restrict__ Bhi, const __nv_bfloat16* __restrict__ Blo,
    const float* __restrict__ asrc, const float* __restrict__ adst,
    const float* __restrict__ bias,
    const float* __restrict__ Wl, const float* __restrict__ bl,
    float* __restrict__ hid, float* __restrict__ yout)
{
    extern __shared__ char smem[];
    const uint32_t sb = smem_to_u32(smem);
    const int tid = threadIdx.x;
    const int wid = tid >> 5, lane = tid & 31;
    const int warpM = wid & 3, warpN = wid >> 2;     // 4 x 2
    const int rowBaseI = blockIdx.x * ROWS_PER_BLK;

    const __nv_bfloat16* srcs[4] = {
        Ahi + (size_t)rowBaseI * F_HID, Alo + (size_t)rowBaseI * F_HID,
        Bhi, Blo
    };

    auto load_stage = [&](int ck, int st) {
        uint32_t base = sb + st * G2_STAGE_B;
        #pragma unroll
        for (int i = 0; i < 8; i++) {
            int id = tid + i * 256;            // 0..2047
            int m  = id >> 9;
            int v  = id & 511;
            int row = v >> 2, c = v & 3;
            int rowc = row;
            if (m < 2 && rowBaseI + rowc >= N_NODES) rowc = N_NODES - 1 - rowBaseI;
            const char* g = (const char*)(srcs[m] + (size_t)rowc * F_HID + ck * 32) + c * 16;
            cp_async16(base + m * 8192 + sw_off(row, c * 16), g);
        }
        CP_COMMIT();
    };

    float acc[2][8][4];
    #pragma unroll
    for (int mt = 0; mt < 2; mt++)
        #pragma unroll
        for (int nt = 0; nt < 8; nt++)
            #pragma unroll
            for (int j = 0; j < 4; j++) acc[mt][nt][j] = 0.f;

    load_stage(0, 0);
    load_stage(1, 1);

    const int q = lane >> 3, r = lane & 7;
    const int aRowBase = warpM * 32 + ((q & 1) ? 8 : 0) + r;
    const int aColSel  = (q & 2) ? 8 : 0;
    const int bRowBase = warpN * 64 + ((q & 2) ? 8 : 0) + r;
    const int bColSel  = (q & 1) ? 8 : 0;

    #pragma unroll
    for (int ck = 0; ck < G2_NK; ck++) {
        if (ck < G2_NK - 1) CP_WAIT1(); else CP_WAIT0();
        __syncthreads();
        if (ck + 2 < G2_NK) load_stage(ck + 2, (ck + 2) % G2_NSTAGE);

        const uint32_t st = sb + (ck % G2_NSTAGE) * G2_STAGE_B;
        #pragma unroll
        for (int ks = 0; ks < 2; ks++) {
            const int k0 = ks * 16;
            uint32_t ah[2][4], al[2][4];
            uint32_t bhf[4][4], blf[4][4];
            #pragma unroll
            for (int mt = 0; mt < 2; mt++) {
                uint32_t a = st + sw_off(aRowBase + mt * 16, (k0 + aColSel) * 2);
                ldsm_x4(a, ah[mt]);
                ldsm_x4(a + 8192, al[mt]);
            }
            #pragma unroll
            for (int nt2 = 0; nt2 < 4; nt2++) {
                uint32_t a = st + 16384 + sw_off(bRowBase + nt2 * 16, (k0 + bColSel) * 2);
                ldsm_x4(a, bhf[nt2]);
                ldsm_x4(a + 8192, blf[nt2]);
            }
            #pragma unroll
            for (int nt2 = 0; nt2 < 4; nt2++) {
                #pragma unroll
                for (int half = 0; half < 2; half++) {
                    const int nt = nt2 * 2 + half;
                    const uint32_t* bhp = bhf[nt2] + half * 2;
                    const uint32_t* blp = blf[nt2] + half * 2;
                    mma_bf16(acc[0][nt], ah[0], bhp);
                    mma_bf16(acc[1][nt], ah[1], bhp);
                    mma_bf16(acc[0][nt], al[0], bhp);
                    mma_bf16(acc[1][nt], al[1], bhp);
                    mma_bf16(acc[0][nt], ah[0], blp);
                    mma_bf16(acc[1][nt], ah[1], blp);
                }
            }
        }
    }

    // ---------------- fused epilogue: agg2 + head ----------------
    __syncthreads();

    float* hs    = (float*)smem;                       // [128][132] = 67584B
    float* sv    = (float*)(smem + 67584);             // 128
    float* dvv   = sv + 128;                           // 128
    float* alpha = dvv + 128;                          // [128][12]
    float* pw    = alpha + 128 * 12;                   // 128
    float* sa    = pw + 128;                           // 128
    float* sd    = sa + 128;                           // 128

    const int g2 = lane >> 2, ti = lane & 3;
    #pragma unroll
    for (int mt = 0; mt < 2; mt++) {
        int row = warpM * 32 + mt * 16 + g2;
        #pragma unroll
        for (int nt = 0; nt < 8; nt++) {
            int col = warpN * 64 + nt * 8 + ti * 2;
            *(float2*)&hs[row * HS2_STRIDE + col]       = make_float2(acc[mt][nt][0], acc[mt][nt][1]);
            *(float2*)&hs[(row + 8) * HS2_STRIDE + col] = make_float2(acc[mt][nt][2], acc[mt][nt][3]);
        }
    }
    if (tid < F_OUT) { sa[tid] = asrc[tid]; sd[tid] = adst[tid]; }
    __syncthreads();

    const int nSess  = min(SESS_PER_BLK, B_SESS - blockIdx.x * SESS_PER_BLK);
    const int nNodes = nSess * NPS;

    // per-node attention dots (float4)
    {
        const float4* sa4 = (const float4*)sa;
        const float4* sd4 = (const float4*)sd;
        float4 s1 = sa4[lane];
        float4 d1 = sd4[lane];
        for (int node = wid; node < nNodes; node += 8) {
            const float4* hp = (const float4*)&hs[node * HS2_STRIDE];
            float4 h1 = hp[lane];
            float ss = h1.x * s1.x + h1.y * s1.y + h1.z * s1.z + h1.w * s1.w;
            float dd = h1.x * d1.x + h1.y * d1.y + h1.z * d1.z + h1.w * d1.w;
            #pragma unroll
            for (int o = 16; o; o >>= 1) {
                ss += __shfl_down_sync(0xffffffffu, ss, o);
                dd += __shfl_down_sync(0xffffffffu, dd, o);
            }
            if (lane == 0) { sv[node] = ss; dvv[node] = dd; }
        }
    }
    __syncthreads();

    if (tid < nNodes) compute_alpha(sv, dvv, alpha, tid);
    __syncthreads();

    // aggregate + bias -> hidden (global), head: one warp covers all 128 cols
    {
        const int col0 = (lane) * 4;            // 32 lanes x 4 = 128 cols
        const float4 bv = *(const float4*)&bias[col0];
        const float4 wv = *(const float4*)&Wl[col0];
        int slot = wid;                          // wid 0..7 < 21
        for (int n = wid; n < nNodes; n += 8) {
            int rbase = n - slot;
            float4 a = aggregate4(hs, HS2_STRIDE, alpha, rbase, slot, col0);
            float v0 = a.x + bv.x, v1 = a.y + bv.y, v2 = a.z + bv.z, v3 = a.w + bv.w;
            *(float4*)&hid[(size_t)(rowBaseI + n) * F_OUT + col0] = make_float4(v0, v1, v2, v3);
            float pp = fmaxf(v0, 0.f) * wv.x + fmaxf(v1, 0.f) * wv.y
                     + fmaxf(v2, 0.f) * wv.z + fmaxf(v3, 0.f) * wv.w;
            #pragma unroll
            for (int o = 16; o; o >>= 1)
                pp += __shfl_down_sync(0xffffffffu, pp, o);
            if (lane == 0) pw[n] = pp;
            slot += 8; if (slot >= NPS) slot -= NPS;
        }
    }
    __syncthreads();

    if (tid < nNodes) {
        float p = pw[tid] + bl[0];
        yout[rowBaseI + tid] = 1.f / (1.f + expf(-p));
    }
}

// ===========================================================================
extern "C" void kernel_launch(void* const* d_in, const int* in_sizes, int n_in,
                              void* d_out, int out_size)
{
    const float* x     = (const float*)d_in[1];
    const int*   click = (const int*)  d_in[4];
    const int*   query = (const int*)  d_in[5];
    const int*   docu  = (const int*)  d_in[6];
    const int*   title = (const int*)  d_in[7];
    const float* qtab  = (const float*)d_in[8];
    const float* dtab  = (const float*)d_in[9];
    const float* ttab  = (const float*)d_in[10];
    const float* ptab  = (const float*)d_in[11];
    const float* ctab  = (const float*)d_in[12];
    const float* W1    = (const float*)d_in[13];
    const float* as1   = (const float*)d_in[14];
    const float* ad1   = (const float*)d_in[15];
    const float* b1    = (const float*)d_in[16];
    const float* W2    = (const float*)d_in[17];
    const float* as2   = (const float*)d_in[18];
    const float* ad2   = (const float*)d_in[19];
    const float* b2    = (const float*)d_in[20];
    const float* Wl    = (const float*)d_in[21];
    const float* bl    = (const float*)d_in[22];

    float* out  = (float*)d_out;
    float* xout = out + OUT_X_OFF;
    float* hout = out + OUT_HID_OFF;
    float* yout = out + OUT_Y_OFF;

    __nv_bfloat16 *xhi, *xlo, *yhi, *ylo, *w1hi, *w1lo, *w2hi, *w2lo;
    cudaGetSymbolAddress((void**)&xhi,  g_xhi);
    cudaGetSymbolAddress((void**)&xlo,  g_xlo);
    cudaGetSymbolAddress((void**)&yhi,  g_yhi);
    cudaGetSymbolAddress((void**)&ylo,  g_ylo);
    cudaGetSymbolAddress((void**)&w1hi, g_w1hi);
    cudaGetSymbolAddress((void**)&w1lo, g_w1lo);
    cudaGetSymbolAddress((void**)&w2hi, g_w2hi);
    cudaGetSymbolAddress((void**)&w2lo, g_w2lo);

    cudaFuncSetAttribute(gemm1_fused, cudaFuncAttributeMaxDynamicSharedMemorySize, G1_SMEM);
    cudaFuncSetAttribute(gemm2_fused, cudaFuncAttributeMaxDynamicSharedMemorySize, G2_SMEM);

    // 1. scatter embeddings into x output slice + fused bf16 hi/lo split
    {
        long long tot = (long long)N_NODES * (K1_PAD / 4);
        build_x_kernel<<<(unsigned)((tot + 255) / 256), 256>>>(
            x, click, query, docu, title, qtab, dtab, ttab, ptab, ctab,
            xout, xhi, xlo);
    }

    // 2. weight splits
    {
        long long tot = (long long)F_HID * K1_PAD;
        conv_split<<<(unsigned)((tot + 255) / 256), 256>>>(W1, F_IN, w1hi, w1lo, K1_PAD, tot);
    }
    {
        long long tot = (long long)F_OUT * F_HID;
        conv_split<<<(unsigned)((tot + 255) / 256), 256>>>(W2, F_HID, w2hi, w2lo, F_HID, tot);
    }

    // 3. fused GEMM1 + agg1 -> y (bf16 hi/lo)
    gemm1_fused<<<G1_NBLK, 256, G1_SMEM>>>(
        xhi, xlo, w1hi, w1lo, as1, ad1, b1, yhi, ylo);

    // 4. fused GEMM2 + agg2 + head -> hidden, y
    gemm2_fused<<<NBLK, 256, G2_SMEM>>>(
        yhi, ylo, w2hi, w2lo, as2, ad2, b2, Wl, bl, hout, yout);
}

// round 17
// speedup vs baseline: 1.1208x; 1.1208x over previous
#include <cuda_runtime.h>
#include <cuda_bf16.h>
#include <cuda_fp16.h>
#include <math.h>
#include <stdint.h>

#define B_SESS   8192
#define NPS      21
#define N_NODES  (B_SESS * NPS)      // 172032
#define F_IN     171
#define K1_PAD   192                 // F_IN padded to 6*32
#define F_HID    256
#define F_OUT    128

// GEMM2 blocking
#define SESS_PER_BLK 6
#define ROWS_PER_BLK (SESS_PER_BLK * NPS)   // 126
#define NBLK ((B_SESS + SESS_PER_BLK - 1) / SESS_PER_BLK)  // 1366

// GEMM1 blocking (3 sessions, 64-row tile, 2 CTAs/SM)
#define G1_SESS 3
#define G1_ROWS (G1_SESS * NPS)             // 63
#define G1_NBLK ((B_SESS + G1_SESS - 1) / G1_SESS)  // 2731

// Output layout: hidden_state (N*128) | y (N*1) | x (N*171)
#define OUT_HID_OFF  0
#define OUT_Y_OFF    ((size_t)N_NODES * F_OUT)
#define OUT_X_OFF    ((size_t)N_NODES * (F_OUT + 1))

// Scratch (static device arrays: allocation-free)
__device__ __half         g_xhi[(size_t)N_NODES * K1_PAD];
__device__ __half         g_xlo[(size_t)N_NODES * K1_PAD];
__device__ __half         g_w1h[(size_t)F_HID * K1_PAD];
__device__ __nv_bfloat16  g_yhi[(size_t)N_NODES * F_HID];
__device__ __nv_bfloat16  g_ylo[(size_t)N_NODES * F_HID];
__device__ __nv_bfloat16  g_w2hi[(size_t)F_OUT * F_HID];
__device__ __nv_bfloat16  g_w2lo[(size_t)F_OUT * F_HID];

// ===========================================================================
// helpers
// ===========================================================================
__device__ __forceinline__ uint32_t smem_to_u32(const void* p) {
    uint32_t a;
    asm("{ .reg .u64 t; cvta.to.shared.u64 t, %1; cvt.u32.u64 %0, t; }" : "=r"(a) : "l"(p));
    return a;
}
__device__ __forceinline__ void cp_async16(uint32_t dst, const void* src) {
    asm volatile("cp.async.cg.shared.global [%0], [%1], 16;" :: "r"(dst), "l"(src));
}
#define CP_COMMIT() asm volatile("cp.async.commit_group;" ::: "memory")
#define CP_WAIT0()  asm volatile("cp.async.wait_group 0;" ::: "memory")
#define CP_WAIT1()  asm volatile("cp.async.wait_group 1;" ::: "memory")

__device__ __forceinline__ void ldsm_x4(uint32_t addr, uint32_t* r) {
    asm volatile("ldmatrix.sync.aligned.m8n8.x4.shared.b16 {%0,%1,%2,%3}, [%4];"
        : "=r"(r[0]), "=r"(r[1]), "=r"(r[2]), "=r"(r[3]) : "r"(addr));
}
__device__ __forceinline__ void mma_bf16(float* d, const uint32_t* a, const uint32_t* b) {
    asm volatile("mma.sync.aligned.m16n8k16.row.col.f32.bf16.bf16.f32 "
        "{%0,%1,%2,%3}, {%4,%5,%6,%7}, {%8,%9}, {%0,%1,%2,%3};"
        : "+f"(d[0]), "+f"(d[1]), "+f"(d[2]), "+f"(d[3])
        : "r"(a[0]), "r"(a[1]), "r"(a[2]), "r"(a[3]), "r"(b[0]), "r"(b[1]));
}
__device__ __forceinline__ void mma_f16(float* d, const uint32_t* a, const uint32_t* b) {
    asm volatile("mma.sync.aligned.m16n8k16.row.col.f32.f16.f16.f32 "
        "{%0,%1,%2,%3}, {%4,%5,%6,%7}, {%8,%9}, {%0,%1,%2,%3};"
        : "+f"(d[0]), "+f"(d[1]), "+f"(d[2]), "+f"(d[3])
        : "r"(a[0]), "r"(a[1]), "r"(a[2]), "r"(a[3]), "r"(b[0]), "r"(b[1]));
}

// XOR bank swizzle on 64B rows (16B chunk granularity)
__device__ __forceinline__ uint32_t sw_off(int row, int colByte) {
    return (uint32_t)(row * 64 + ((((colByte >> 4) ^ ((row >> 1) & 3)) & 3) << 4));
}

__device__ __forceinline__ float lrelu(float v) { return v > 0.f ? v : 0.2f * v; }

// Branch-specialized softmax over in-neighbors (no local arrays).
__device__ __forceinline__ void compute_alpha(
    const float* __restrict__ sv, const float* __restrict__ dvv,
    float* __restrict__ alpha, int node)
{
    int slot = node % NPS;
    int rbase = node - slot;
    float d = dvv[node];
    float* al = alpha + node * 12;
    if (slot == 0) {
        float e0 = lrelu(sv[rbase + 1] + d);
        float e1 = lrelu(sv[rbase + 2] + d);
        float e2 = lrelu(sv[rbase + 3] + d);
        float e3 = lrelu(sv[rbase + 4] + d);
        float e4 = lrelu(sv[rbase + 5] + d);
        float e5 = lrelu(sv[rbase + 6] + d);
        float e6 = lrelu(sv[rbase + 7] + d);
        float e7 = lrelu(sv[rbase + 8] + d);
        float e8 = lrelu(sv[rbase + 9] + d);
        float e9 = lrelu(sv[rbase + 10] + d);
        float ea = lrelu(sv[rbase + 0] + d);
        float m = fmaxf(ea, fmaxf(fmaxf(fmaxf(e0, e1), fmaxf(e2, e3)),
                  fmaxf(fmaxf(fmaxf(e4, e5), fmaxf(e6, e7)), fmaxf(e8, e9))));
        e0 = expf(e0 - m); e1 = expf(e1 - m); e2 = expf(e2 - m); e3 = expf(e3 - m);
        e4 = expf(e4 - m); e5 = expf(e5 - m); e6 = expf(e6 - m); e7 = expf(e7 - m);
        e8 = expf(e8 - m); e9 = expf(e9 - m); ea = expf(ea - m);
        float inv = 1.f / (e0 + e1 + e2 + e3 + e4 + e5 + e6 + e7 + e8 + e9 + ea);
        al[0] = e0 * inv; al[1] = e1 * inv; al[2] = e2 * inv; al[3] = e3 * inv;
        al[4] = e4 * inv; al[5] = e5 * inv; al[6] = e6 * inv; al[7] = e7 * inv;
        al[8] = e8 * inv; al[9] = e9 * inv; al[10] = ea * inv;
    } else if (slot <= 10) {
        float v0 = lrelu(sv[rbase] + d);
        float v1 = lrelu(sv[rbase + slot + 10] + d);
        float v2 = lrelu(sv[rbase + slot] + d);
        float m = fmaxf(v0, fmaxf(v1, v2));
        float e0 = expf(v0 - m), e1 = expf(v1 - m), e2 = expf(v2 - m);
        float inv = 1.f / (e0 + e1 + e2);
        al[0] = e0 * inv; al[1] = e1 * inv; al[2] = e2 * inv;
    } else {
        float v0 = lrelu(sv[rbase + slot - 10] + d);
        float v1 = lrelu(sv[rbase + slot] + d);
        float m = fmaxf(v0, v1);
        float e0 = expf(v0 - m), e1 = expf(v1 - m);
        float inv = 1.f / (e0 + e1);
        al[0] = e0 * inv; al[1] = e1 * inv;
    }
}

// Branch-specialized 4-column aggregation (float4, explicit slot).
__device__ __forceinline__ float4 aggregate4(
    const float* __restrict__ hs, int stride,
    const float* __restrict__ alpha, int rbase, int slot, int col0)
{
    const float* al = alpha + (rbase + slot) * 12;
    float4 a = make_float4(0.f, 0.f, 0.f, 0.f);
    if (slot == 0) {
        #pragma unroll
        for (int j = 0; j < 10; j++) {
            float4 h = *(const float4*)&hs[(rbase + 1 + j) * stride + col0];
            float w = al[j];
            a.x = fmaf(w, h.x, a.x); a.y = fmaf(w, h.y, a.y);
            a.z = fmaf(w, h.z, a.z); a.w = fmaf(w, h.w, a.w);
        }
        float4 h = *(const float4*)&hs[rbase * stride + col0];
        float w = al[10];
        a.x = fmaf(w, h.x, a.x); a.y = fmaf(w, h.y, a.y);
        a.z = fmaf(w, h.z, a.z); a.w = fmaf(w, h.w, a.w);
    } else if (slot <= 10) {
        float4 h0 = *(const float4*)&hs[rbase * stride + col0];
        float4 h1 = *(const float4*)&hs[(rbase + slot + 10) * stride + col0];
        float4 h2 = *(const float4*)&hs[(rbase + slot) * stride + col0];
        float w0 = al[0], w1 = al[1], w2 = al[2];
        a.x = w0 * h0.x + w1 * h1.x + w2 * h2.x;
        a.y = w0 * h0.y + w1 * h1.y + w2 * h2.y;
        a.z = w0 * h0.z + w1 * h1.z + w2 * h2.z;
        a.w = w0 * h0.w + w1 * h1.w + w2 * h2.w;
    } else {
        float4 h0 = *(const float4*)&hs[(rbase + slot - 10) * stride + col0];
        float4 h1 = *(const float4*)&hs[(rbase + slot) * stride + col0];
        float w0 = al[0], w1 = al[1];
        a.x = w0 * h0.x + w1 * h1.x;
        a.y = w0 * h0.y + w1 * h1.y;
        a.z = w0 * h0.z + w1 * h1.z;
        a.w = w0 * h0.w + w1 * h1.w;
    }
    return a;
}

// fp16 hi/lo pack (4 values)
__device__ __forceinline__ uint2 pack_hi_lo4_f16(float v0, float v1, float v2, float v3,
                                                 uint2& lo_out)
{
    __half h0 = __float2half(v0), h1 = __float2half(v1);
    __half h2 = __float2half(v2), h3 = __float2half(v3);
    __half l0 = __float2half(v0 - __half2float(h0));
    __half l1 = __float2half(v1 - __half2float(h1));
    __half l2 = __float2half(v2 - __half2float(h2));
    __half l3 = __float2half(v3 - __half2float(h3));
    __half2 h01(h0, h1), h23(h2, h3), l01(l0, l1), l23(l2, l3);
    uint2 hi;
    hi.x = *reinterpret_cast<uint32_t*>(&h01);
    hi.y = *reinterpret_cast<uint32_t*>(&h23);
    lo_out.x = *reinterpret_cast<uint32_t*>(&l01);
    lo_out.y = *reinterpret_cast<uint32_t*>(&l23);
    return hi;
}

// bf16 hi/lo pack (4 values)
__device__ __forceinline__ uint2 pack_hi_lo4_bf16(float v0, float v1, float v2, float v3,
                                                  uint2& lo_out)
{
    __nv_bfloat16 h0 = __float2bfloat16(v0), h1 = __float2bfloat16(v1);
    __nv_bfloat16 h2 = __float2bfloat16(v2), h3 = __float2bfloat16(v3);
    __nv_bfloat16 l0 = __float2bfloat16(v0 - __bfloat162float(h0));
    __nv_bfloat16 l1 = __float2bfloat16(v1 - __bfloat162float(h1));
    __nv_bfloat16 l2 = __float2bfloat16(v2 - __bfloat162float(h2));
    __nv_bfloat16 l3 = __float2bfloat16(v3 - __bfloat162float(h3));
    __nv_bfloat162 h01(h0, h1), h23(h2, h3), l01(l0, l1), l23(l2, l3);
    uint2 hi;
    hi.x = *reinterpret_cast<uint32_t*>(&h01);
    hi.y = *reinterpret_cast<uint32_t*>(&h23);
    lo_out.x = *reinterpret_cast<uint32_t*>(&l01);
    lo_out.y = *reinterpret_cast<uint32_t*>(&l23);
    return hi;
}

// ===========================================================================
// Kernel 1: build x_mod (scatter) + fused fp16 hi/lo split, 4 cols per thread
// ===========================================================================
__global__ __launch_bounds__(256) void build_x_kernel(
    const float* __restrict__ x,
    const int*   __restrict__ click,
    const int*   __restrict__ query,
    const int*   __restrict__ docu,
    const int*   __restrict__ title_id,
    const float* __restrict__ qtab,
    const float* __restrict__ dtab,
    const float* __restrict__ ttab,
    const float* __restrict__ ptab,
    const float* __restrict__ ctab,
    float* __restrict__ xout,
    __half* __restrict__ xhi,
    __half* __restrict__ xlo)
{
    long long t = (long long)blockIdx.x * blockDim.x + threadIdx.x;
    if (t >= (long long)N_NODES * (K1_PAD / 4)) return;
    int n  = (int)(t / (K1_PAD / 4));
    int cc = (int)(t - (long long)n * (K1_PAD / 4));
    int c0 = cc * 4;
    int b = n / NPS;
    int s = n - b * NPS;

    float4 v;
    if (c0 + 3 < 160) {
        const float* tab;
        size_t row;
        if (s == 0)            { tab = qtab; row = (size_t)query[b]; }
        else if (s <= 10)      { tab = dtab; row = (size_t)docu[b * 10 + (s - 1)]; }
        else                   { tab = ttab; row = (size_t)title_id[b * 10 + (s - 11)]; }
        v = *(const float4*)(tab + row * 160 + c0);
    } else {
        float vv[4];
        #pragma unroll
        for (int j = 0; j < 4; j++) {
            int c = c0 + j;
            float val = 0.f;
            if (c < F_IN) {
                long long xi = (long long)n * F_IN + c;
                if (s == 0) {
                    val = (c < 160) ? qtab[(size_t)query[b] * 160 + c] : x[xi];
                } else if (s <= 10) {
                    int jj = s - 1;
                    if      (c < 160)  val = dtab[(size_t)docu[b * 10 + jj] * 160 + c];
                    else if (c == 160) val = ptab[jj];
                    else if (c == 161) val = ctab[click[b]];
                    else               val = x[xi];
                } else {
                    val = (c < 160) ? ttab[(size_t)title_id[b * 10 + (s - 11)] * 160 + c] : x[xi];
                }
            }
            vv[j] = val;
        }
        v = make_float4(vv[0], vv[1], vv[2], vv[3]);
    }

    {
        long long xi = (long long)n * F_IN + c0;
        if (c0 + 3 < F_IN) {
            xout[xi] = v.x; xout[xi + 1] = v.y; xout[xi + 2] = v.z; xout[xi + 3] = v.w;
        } else {
            float vv[4] = {v.x, v.y, v.z, v.w};
            #pragma unroll
            for (int j = 0; j < 4; j++)
                if (c0 + j < F_IN) xout[xi + j] = vv[j];
        }
    }

    long long oi = (long long)n * K1_PAD + c0;
    uint2 lo;
    uint2 hi = pack_hi_lo4_f16(v.x, v.y, v.z, v.w, lo);
    *(uint2*)(xhi + oi) = hi;
    *(uint2*)(xlo + oi) = lo;
}

// ===========================================================================
// Kernel 2a: W1 fp32 -> single fp16 (with K padding)
// ===========================================================================
__global__ __launch_bounds__(256) void conv_w1_f16(
    const float* __restrict__ src, __half* __restrict__ dst, long long total)
{
    long long idx = (long long)blockIdx.x * blockDim.x + threadIdx.x;
    if (idx >= total) return;
    long long row = idx / K1_PAD;
    int c = (int)(idx - row * K1_PAD);
    float v = (c < F_IN) ? src[row * F_IN + c] : 0.f;
    dst[idx] = __float2half(v);
}

// ===========================================================================
// Kernel 2b: W2 fp32 -> bf16 hi/lo split
// ===========================================================================
__global__ __launch_bounds__(256) void conv_w2_split(
    const float* __restrict__ src,
    __nv_bfloat16* __restrict__ hi, __nv_bfloat16* __restrict__ lo, long long total)
{
    long long idx = (long long)blockIdx.x * blockDim.x + threadIdx.x;
    if (idx >= total) return;
    float v = src[idx];
    __nv_bfloat16 h = __float2bfloat16(v);
    hi[idx] = h;
    lo[idx] = __float2bfloat16(v - __bfloat162float(h));
}

// ===========================================================================
// Kernel 3: fused GEMM1 (x @ W1^T, fp16 2-product HMMA) + GAT agg layer 1
// Block: 256 thr, 8 warps (2x4), tile 64(63 used) x 256, K=192. 3-stage.
// ===========================================================================
#define G1_NK 6
#define G1_ARRA 4096            // 64 rows x 64B
#define G1_ARRB 16384           // 256 rows x 64B
#define G1_STAGE_B (2 * G1_ARRA + G1_ARRB)   // 24576: Ah, Al, B
#define G1_NSTAGE 3
#define G1_SMEM (G1_NSTAGE * G1_STAGE_B)     // 73728
#define HS1_STRIDE 260

__global__ __launch_bounds__(256, 2) void gemm1_fused(
    const __half* __restrict__ Ahi, const __half* __restrict__ Alo,
    const __half* __restrict__ Bh,
    const float* __restrict__ asrc, const float* __restrict__ adst,
    const float* __restrict__ bias,
    __nv_bfloat16* __restrict__ Yhi, __nv_bfloat16* __restrict__ Ylo)
{
    extern __shared__ char smem[];
    const uint32_t sb = smem_to_u32(smem);
    const int tid = threadIdx.x;
    const int wid = tid >> 5, lane = tid & 31;
    const int warpM = wid & 1, warpN = wid >> 1;     // 2 x 4 warp grid
    const int rowBaseI = blockIdx.x * G1_ROWS;

    const __half* srcA[2] = { Ahi + (size_t)rowBaseI * K1_PAD,
                              Alo + (size_t)rowBaseI * K1_PAD };

    auto load_stage = [&](int ck, int st) {
        uint32_t base = sb + st * G1_STAGE_B;
        #pragma unroll
        for (int i = 0; i < 6; i++) {
            int id = tid + i * 256;            // 0..1535
            if (id < 512) {                    // A arrays: 2 x 64 rows
                int m = id >> 8;
                int v = id & 255;
                int row = v >> 2, c = v & 3;
                int rowc = row;
                if (rowBaseI + rowc >= N_NODES) rowc = N_NODES - 1 - rowBaseI;
                const char* g = (const char*)(srcA[m] + (size_t)rowc * K1_PAD + ck * 32) + c * 16;
                cp_async16(base + m * G1_ARRA + sw_off(row, c * 16), g);
            } else {                           // B array: 256 rows
                int idb = id - 512;            // 0..1023
                int row = idb >> 2, c = idb & 3;
                const char* g = (const char*)(Bh + (size_t)row * K1_PAD + ck * 32) + c * 16;
                cp_async16(base + 2 * G1_ARRA + sw_off(row, c * 16), g);
            }
        }
        CP_COMMIT();
    };

    float acc[2][8][4];
    #pragma unroll
    for (int mt = 0; mt < 2; mt++)
        #pragma unroll
        for (int nt = 0; nt < 8; nt++)
            #pragma unroll
            for (int j = 0; j < 4; j++) acc[mt][nt][j] = 0.f;

    load_stage(0, 0);
    load_stage(1, 1);

    const int q = lane >> 3, r = lane & 7;
    const int aRowBase = warpM * 32 + ((q & 1) ? 8 : 0) + r;
    const int aColSel  = (q & 2) ? 8 : 0;
    const int bRowBase = warpN * 64 + ((q & 2) ? 8 : 0) + r;
    const int bColSel  = (q & 1) ? 8 : 0;

    #pragma unroll
    for (int ck = 0; ck < G1_NK; ck++) {
        if (ck < G1_NK - 1) CP_WAIT1(); else CP_WAIT0();
        __syncthreads();
        if (ck + 2 < G1_NK) load_stage(ck + 2, (ck + 2) % G1_NSTAGE);

        const uint32_t st = sb + (ck % G1_NSTAGE) * G1_STAGE_B;
        #pragma unroll
        for (int ks = 0; ks < 2; ks++) {
            const int k0 = ks * 16;
            uint32_t ah[2][4], al[2][4];
            #pragma unroll
            for (int mt = 0; mt < 2; mt++) {
                uint32_t a = st + sw_off(aRowBase + mt * 16, (k0 + aColSel) * 2);
                ldsm_x4(a, ah[mt]);
                ldsm_x4(a + G1_ARRA, al[mt]);
            }
            #pragma unroll
            for (int nt2 = 0; nt2 < 4; nt2++) {
                uint32_t a = st + 2 * G1_ARRA + sw_off(bRowBase + nt2 * 16, (k0 + bColSel) * 2);
                uint32_t bf[4];
                ldsm_x4(a, bf);
                #pragma unroll
                for (int half = 0; half < 2; half++) {
                    const int nt = nt2 * 2 + half;
                    const uint32_t* bp = bf + half * 2;
                    mma_f16(acc[0][nt], ah[0], bp);
                    mma_f16(acc[1][nt], ah[1], bp);
                    mma_f16(acc[0][nt], al[0], bp);
                    mma_f16(acc[1][nt], al[1], bp);
                }
            }
        }
    }

    // ---------------- fused epilogue: GAT aggregation ----------------
    __syncthreads();   // all warps done reading stages: reuse smem

    float* hs    = (float*)smem;                       // [64][260] = 66560B
    float* sv    = (float*)(smem + 66560);             // 64
    float* dvv   = sv + 64;                            // 64
    float* alpha = dvv + 64;                           // [64][12]
    float* sa    = alpha + 64 * 12;                    // 256
    float* sd    = sa + 256;                           // 256  (ends at 72192 <= 73728)

    const int g2 = lane >> 2, ti = lane & 3;
    #pragma unroll
    for (int mt = 0; mt < 2; mt++) {
        int row = warpM * 32 + mt * 16 + g2;
        #pragma unroll
        for (int nt = 0; nt < 8; nt++) {
            int col = warpN * 64 + nt * 8 + ti * 2;
            *(float2*)&hs[row * HS1_STRIDE + col]       = make_float2(acc[mt][nt][0], acc[mt][nt][1]);
            *(float2*)&hs[(row + 8) * HS1_STRIDE + col] = make_float2(acc[mt][nt][2], acc[mt][nt][3]);
        }
    }
    if (tid < F_HID) { sa[tid] = asrc[tid]; sd[tid] = adst[tid]; }
    __syncthreads();

    const int nSess  = min(G1_SESS, B_SESS - blockIdx.x * G1_SESS);
    const int nNodes = nSess * NPS;

    // per-node attention dots (float4, smem-staged a-vectors)
    {
        const float4* sa4 = (const float4*)sa;
        const float4* sd4 = (const float4*)sd;
        float4 s1 = sa4[lane], s2 = sa4[32 + lane];
        float4 d1 = sd4[lane], d2 = sd4[32 + lane];
        for (int node = wid; node < nNodes; node += 8) {
            const float4* hp = (const float4*)&hs[node * HS1_STRIDE];
            float4 h1 = hp[lane], h2 = hp[32 + lane];
            float ss = h1.x * s1.x + h1.y * s1.y + h1.z * s1.z + h1.w * s1.w
                     + h2.x * s2.x + h2.y * s2.y + h2.z * s2.z + h2.w * s2.w;
            float dd = h1.x * d1.x + h1.y * d1.y + h1.z * d1.z + h1.w * d1.w
                     + h2.x * d2.x + h2.y * d2.y + h2.z * d2.z + h2.w * d2.w;
            #pragma unroll
            for (int o = 16; o; o >>= 1) {
                ss += __shfl_down_sync(0xffffffffu, ss, o);
                dd += __shfl_down_sync(0xffffffffu, dd, o);
            }
            if (lane == 0) { sv[node] = ss; dvv[node] = dd; }
        }
    }
    __syncthreads();

    if (tid < nNodes) compute_alpha(sv, dvv, alpha, tid);
    __syncthreads();

    // aggregate + bias + relu -> y bf16 hi/lo (4 cols per thread)
    {
        const int col0 = (tid & 63) * 4;
        const int hgrp = tid >> 6;              // 0..3 (warp-uniform)
        const float4 bv = *(const float4*)&bias[col0];
        int slot = hgrp;
        for (int n = hgrp; n < nNodes; n += 4) {
            int rbase = n - slot;
            float4 a = aggregate4(hs, HS1_STRIDE, alpha, rbase, slot, col0);
            float v0 = fmaxf(a.x + bv.x, 0.f);
            float v1 = fmaxf(a.y + bv.y, 0.f);
            float v2 = fmaxf(a.z + bv.z, 0.f);
            float v3 = fmaxf(a.w + bv.w, 0.f);
            uint2 lo;
            uint2 hi = pack_hi_lo4_bf16(v0, v1, v2, v3, lo);
            size_t off = (size_t)(rowBaseI + n) * F_HID + col0;
            *(uint2*)(Yhi + off) = hi;
            *(uint2*)(Ylo + off) = lo;
            slot += 4; if (slot >= NPS) slot -= NPS;
        }
    }
}

// ===========================================================================
// Kernel 4: fused GEMM2 (y @ W2^T, bf16 split-3) + GAT agg layer 2 + head
// Block: 256 thr, 8 warps (4x2), tile 128(126) x 128, K=256. 3-stage.
// ===========================================================================
#define G2_NK 8
#define G2_STAGE_B 32768        // Ahi Alo Bhi Blo: 4 x 8192
#define G2_NSTAGE 3
#define G2_SMEM (G2_NSTAGE * G2_STAGE_B)   // 98304
#define HS2_STRIDE 132

__global__ __launch_bounds__(256, 2) void gemm2_fused(
    const __nv_bfloat16* __restrict__ Ahi, const __nv_bfloat16* __restrict__ Alo,
    const __nv_bfloat16* __restrict__ Bhi, const __nv_bfloat16* __restrict__ Blo,
    const float* __restrict__ asrc, const float* __restrict__ adst,
    const float* __restrict__ bias,
    const float* __restrict__ Wl, const float* __restrict__ bl,
    float* __restrict__ hid, float* __restrict__ yout)
{
    extern __shared__ char smem[];
    const uint32_t sb = smem_to_u32(smem);
    const int tid = threadIdx.x;
    const int wid = tid >> 5, lane = tid & 31;
    const int warpM = wid & 3, warpN = wid >> 2;     // 4 x 2
    const int rowBaseI = blockIdx.x * ROWS_PER_BLK;

    const __nv_bfloat16* srcs[4] = {
        Ahi + (size_t)rowBaseI * F_HID, Alo + (size_t)rowBaseI * F_HID,
        Bhi, Blo
    };

    auto load_stage = [&](int ck, int st) {
        uint32_t base = sb + st * G2_STAGE_B;
        #pragma unroll
        for (int i = 0; i < 8; i++) {
            int id = tid + i * 256;            // 0..2047
            int m  = id >> 9;
            int v  = id & 511;
            int row = v >> 2, c = v & 3;
            int rowc = row;
            if (m < 2 && rowBaseI + rowc >= N_NODES) rowc = N_NODES - 1 - rowBaseI;
            const char* g = (const char*)(srcs[m] + (size_t)rowc * F_HID + ck * 32) + c * 16;
            cp_async16(base + m * 8192 + sw_off(row, c * 16), g);
        }
        CP_COMMIT();
    };

    float acc[2][8][4];
    #pragma unroll
    for (int mt = 0; mt < 2; mt++)
        #pragma unroll
        for (int nt = 0; nt < 8; nt++)
            #pragma unroll
            for (int j = 0; j < 4; j++) acc[mt][nt][j] = 0.f;

    load_stage(0, 0);
    load_stage(1, 1);

    const int q = lane >> 3, r = lane & 7;
    const int aRowBase = warpM * 32 + ((q & 1) ? 8 : 0) + r;
    const int aColSel  = (q & 2) ? 8 : 0;
    const int bRowBase = warpN * 64 + ((q & 2) ? 8 : 0) + r;
    const int bColSel  = (q & 1) ? 8 : 0;

    #pragma unroll
    for (int ck = 0; ck < G2_NK; ck++) {
        if (ck < G2_NK - 1) CP_WAIT1(); else CP_WAIT0();
        __syncthreads();
        if (ck + 2 < G2_NK) load_stage(ck + 2, (ck + 2) % G2_NSTAGE);

        const uint32_t st = sb + (ck % G2_NSTAGE) * G2_STAGE_B;
        #pragma unroll
        for (int ks = 0; ks < 2; ks++) {
            const int k0 = ks * 16;
            uint32_t ah[2][4], al[2][4];
            #pragma unroll
            for (int mt = 0; mt < 2; mt++) {
                uint32_t a = st + sw_off(aRowBase + mt * 16, (k0 + aColSel) * 2);
                ldsm_x4(a, ah[mt]);
                ldsm_x4(a + 8192, al[mt]);
            }
            #pragma unroll
            for (int nt2 = 0; nt2 < 4; nt2++) {
                uint32_t a = st + 16384 + sw_off(bRowBase + nt2 * 16, (k0 + bColSel) * 2);
                uint32_t bh[4], bl_[4];
                ldsm_x4(a, bh);
                ldsm_x4(a + 8192, bl_);
                #pragma unroll
                for (int half = 0; half < 2; half++) {
                    const int nt = nt2 * 2 + half;
                    const uint32_t* bhp = bh + half * 2;
                    const uint32_t* blp = bl_ + half * 2;
                    mma_bf16(acc[0][nt], ah[0], bhp);
                    mma_bf16(acc[1][nt], ah[1], bhp);
                    mma_bf16(acc[0][nt], al[0], bhp);
                    mma_bf16(acc[1][nt], al[1], bhp);
                    mma_bf16(acc[0][nt], ah[0], blp);
                    mma_bf16(acc[1][nt], ah[1], blp);
                }
            }
        }
    }

    // ---------------- fused epilogue: agg2 + head ----------------
    __syncthreads();

    float* hs    = (float*)smem;                       // [128][132] = 67584B
    float* sv    = (float*)(smem + 67584);             // 128
    float* dvv   = sv + 128;                           // 128
    float* alpha = dvv + 128;                          // [128][12]
    float* pw    = alpha + 128 * 12;                   // 128
    float* sa    = pw + 128;                           // 128
    float* sd    = sa + 128;                           // 128

    const int g2 = lane >> 2, ti = lane & 3;
    #pragma unroll
    for (int mt = 0; mt < 2; mt++) {
        int row = warpM * 32 + mt * 16 + g2;
        #pragma unroll
        for (int nt = 0; nt < 8; nt++) {
            int col = warpN * 64 + nt * 8 + ti * 2;
            *(float2*)&hs[row * HS2_STRIDE + col]       = make_float2(acc[mt][nt][0], acc[mt][nt][1]);
            *(float2*)&hs[(row + 8) * HS2_STRIDE + col] = make_float2(acc[mt][nt][2], acc[mt][nt][3]);
        }
    }
    if (tid < F_OUT) { sa[tid] = asrc[tid]; sd[tid] = adst[tid]; }
    __syncthreads();

    const int nSess  = min(SESS_PER_BLK, B_SESS - blockIdx.x * SESS_PER_BLK);
    const int nNodes = nSess * NPS;

    // per-node attention dots (float4)
    {
        const float4* sa4 = (const float4*)sa;
        const float4* sd4 = (const float4*)sd;
        float4 s1 = sa4[lane];
        float4 d1 = sd4[lane];
        for (int node = wid; node < nNodes; node += 8) {
            const float4* hp = (const float4*)&hs[node * HS2_STRIDE];
            float4 h1 = hp[lane];
            float ss = h1.x * s1.x + h1.y * s1.y + h1.z * s1.z + h1.w * s1.w;
            float dd = h1.x * d1.x + h1.y * d1.y + h1.z * d1.z + h1.w * d1.w;
            #pragma unroll
            for (int o = 16; o; o >>= 1) {
                ss += __shfl_down_sync(0xffffffffu, ss, o);
                dd += __shfl_down_sync(0xffffffffu, dd, o);
            }
            if (lane == 0) { sv[node] = ss; dvv[node] = dd; }
        }
    }
    __syncthreads();

    if (tid < nNodes) compute_alpha(sv, dvv, alpha, tid);
    __syncthreads();

    // aggregate + bias -> hidden (global), head: one warp covers all 128 cols
    {
        const int col0 = (lane) * 4;            // 32 lanes x 4 = 128 cols
        const float4 bv = *(const float4*)&bias[col0];
        const float4 wv = *(const float4*)&Wl[col0];
        int slot = wid;                          // wid 0..7 < 21
        for (int n = wid; n < nNodes; n += 8) {
            int rbase = n - slot;
            float4 a = aggregate4(hs, HS2_STRIDE, alpha, rbase, slot, col0);
            float v0 = a.x + bv.x, v1 = a.y + bv.y, v2 = a.z + bv.z, v3 = a.w + bv.w;
            *(float4*)&hid[(size_t)(rowBaseI + n) * F_OUT + col0] = make_float4(v0, v1, v2, v3);
            float pp = fmaxf(v0, 0.f) * wv.x + fmaxf(v1, 0.f) * wv.y
                     + fmaxf(v2, 0.f) * wv.z + fmaxf(v3, 0.f) * wv.w;
            #pragma unroll
            for (int o = 16; o; o >>= 1)
                pp += __shfl_down_sync(0xffffffffu, pp, o);
            if (lane == 0) pw[n] = pp;
            slot += 8; if (slot >= NPS) slot -= NPS;
        }
    }
    __syncthreads();

    if (tid < nNodes) {
        float p = pw[tid] + bl[0];
        yout[rowBaseI + tid] = 1.f / (1.f + expf(-p));
    }
}

// ===========================================================================
extern "C" void kernel_launch(void* const* d_in, const int* in_sizes, int n_in,
                              void* d_out, int out_size)
{
    const float* x     = (const float*)d_in[1];
    const int*   click = (const int*)  d_in[4];
    const int*   query = (const int*)  d_in[5];
    const int*   docu  = (const int*)  d_in[6];
    const int*   title = (const int*)  d_in[7];
    const float* qtab  = (const float*)d_in[8];
    const float* dtab  = (const float*)d_in[9];
    const float* ttab  = (const float*)d_in[10];
    const float* ptab  = (const float*)d_in[11];
    const float* ctab  = (const float*)d_in[12];
    const float* W1    = (const float*)d_in[13];
    const float* as1   = (const float*)d_in[14];
    const float* ad1   = (const float*)d_in[15];
    const float* b1    = (const float*)d_in[16];
    const float* W2    = (const float*)d_in[17];
    const float* as2   = (const float*)d_in[18];
    const float* ad2   = (const float*)d_in[19];
    const float* b2    = (const float*)d_in[20];
    const float* Wl    = (const float*)d_in[21];
    const float* bl    = (const float*)d_in[22];

    float* out  = (float*)d_out;
    float* xout = out + OUT_X_OFF;
    float* hout = out + OUT_HID_OFF;
    float* yout = out + OUT_Y_OFF;

    __half *xhi, *xlo, *w1h;
    __nv_bfloat16 *yhi, *ylo, *w2hi, *w2lo;
    cudaGetSymbolAddress((void**)&xhi,  g_xhi);
    cudaGetSymbolAddress((void**)&xlo,  g_xlo);
    cudaGetSymbolAddress((void**)&w1h,  g_w1h);
    cudaGetSymbolAddress((void**)&yhi,  g_yhi);
    cudaGetSymbolAddress((void**)&ylo,  g_ylo);
    cudaGetSymbolAddress((void**)&w2hi, g_w2hi);
    cudaGetSymbolAddress((void**)&w2lo, g_w2lo);

    cudaFuncSetAttribute(gemm1_fused, cudaFuncAttributeMaxDynamicSharedMemorySize, G1_SMEM);
    cudaFuncSetAttribute(gemm2_fused, cudaFuncAttributeMaxDynamicSharedMemorySize, G2_SMEM);

    // 1. scatter embeddings into x output slice + fused fp16 hi/lo split
    {
        long long tot = (long long)N_NODES * (K1_PAD / 4);
        build_x_kernel<<<(unsigned)((tot + 255) / 256), 256>>>(
            x, click, query, docu, title, qtab, dtab, ttab, ptab, ctab,
            xout, xhi, xlo);
    }

    // 2. weight conversions
    {
        long long tot = (long long)F_HID * K1_PAD;
        conv_w1_f16<<<(unsigned)((tot + 255) / 256), 256>>>(W1, w1h, tot);
    }
    {
        long long tot = (long long)F_OUT * F_HID;
        conv_w2_split<<<(unsigned)((tot + 255) / 256), 256>>>(W2, w2hi, w2lo, tot);
    }

    // 3. fused GEMM1 (fp16 2-product) + agg1 -> y (bf16 hi/lo)
    gemm1_fused<<<G1_NBLK, 256, G1_SMEM>>>(
        xhi, xlo, w1h, as1, ad1, b1, yhi, ylo);

    // 4. fused GEMM2 (bf16 split-3) + agg2 + head -> hidden, y
    gemm2_fused<<<NBLK, 256, G2_SMEM>>>(
        yhi, ylo, w2hi, w2lo, as2, ad2, b2, Wl, bl, hout, yout);
}